// round 14
// baseline (speedup 1.0000x reference)
#include <cuda_runtime.h>
#include <cuda_fp16.h>
#include <cstdint>
#include <math.h>

#define Bdim 64
#define Idim 2048
#define Hdim 2048
#define Tdim 128
#define Mtot (Tdim * Bdim)          // 8192 rows (t,b)

// ---------------- scratch (device globals; allocation-free) ----------------
__device__ __half g_Ah[(size_t)Mtot * Idim];          // 32 MB  [t*B+b][i]
__device__ __half g_w0[(size_t)Hdim * Idim];          // 8 MB   hi plane [h][i]
__device__ __half g_w1[(size_t)Hdim * Idim];          // 8 MB   res*2^11 [h][i]
__device__ float  g_weightedT[(size_t)Tdim * Hdim * Bdim];  // 64 MB [t][h][b]

// ---------------------------------------------------------------------------
// Fused prep, 128B loads AND stores. (R13 verbatim)
// ---------------------------------------------------------------------------
__global__ __launch_bounds__(256) void prep_kernel(const float* __restrict__ in,
                                                   const float* __restrict__ w,
                                                   const float* __restrict__ s) {
    __shared__ float tile[64][33];
    int bid = blockIdx.x;
    int tx = threadIdx.x, ty = threadIdx.y;
    int tid = ty * 32 + tx;
    int orow = tid >> 3;              // 0..31 output row
    int ic0  = (tid & 7) * 8;         // 0..56 i-column base

    if (bid < 8192) {
        int t0 = (bid & 3) * 32;
        int i0 = ((bid >> 2) & 31) * 64;
        int b  = bid >> 7;
#pragma unroll
        for (int j = 0; j < 8; j++)
            tile[ty + j * 8][tx] = in[((size_t)b * Idim + i0 + ty + j * 8) * Tdim + t0 + tx];
        __syncthreads();
        __half h[8];
#pragma unroll
        for (int q = 0; q < 8; q++)
            h[q] = __float2half_rn(tile[ic0 + q][orow]);
        *reinterpret_cast<uint4*>(
            g_Ah + ((size_t)(t0 + orow) * Bdim + b) * Idim + i0 + ic0)
            = *reinterpret_cast<uint4*>(h);
    } else {
        int sid = bid - 8192;
        int i0 = (sid & 31) * 64;
        int h0 = (sid >> 5) * 32;
#pragma unroll
        for (int j = 0; j < 8; j++) {
            size_t idx = (size_t)(i0 + ty + j * 8) * Hdim + h0 + tx;
            tile[ty + j * 8][tx] = w[idx] * s[idx];
        }
        __syncthreads();
        __half hh[8], hl[8];
#pragma unroll
        for (int q = 0; q < 8; q++) {
            float v = tile[ic0 + q][orow];
            __half hi = __float2half_rn(v);
            float r = v - __half2float(hi);             // exact (Fast2Sum)
            hh[q] = hi;
            hl[q] = __float2half_rn(r * 2048.0f);
        }
        size_t o = (size_t)(h0 + orow) * Idim + i0 + ic0;
        *reinterpret_cast<uint4*>(g_w0 + o) = *reinterpret_cast<uint4*>(hh);
        *reinterpret_cast<uint4*>(g_w1 + o) = *reinterpret_cast<uint4*>(hl);
    }
}

// ---------------------------------------------------------------------------
// mma.sync GEMM: C = A @ W0^T + 2^-11 * (A @ W1^T), fp32 acc.
// CTA 64x128, BK=32, 256 threads (8 warps, warp tile 16x64), 3-stage
// cp.async pipeline, ldmatrix.x4, fused 128-kt loop (plane switch kt=64).
// 4 CTAs/SM (46 KB smem each) — quarter-tile granularity experiment.
// Per-element k-accumulation order identical to R13 -> bit-identical output.
// ---------------------------------------------------------------------------
#define BM 64
#define BN 128
#define BK 32
#define ASTR 40                          // halves per smem row (80 B; 5 coprime 8)
#define A_STG_B (BM * ASTR * 2)          // 5120 B
#define B_STG_B (BN * ASTR * 2)          // 10240 B
#define STAGE_BYTES (A_STG_B + B_STG_B)  // 15360 B
#define GEMM_SMEM (3 * STAGE_BYTES)      // 46080 B
#define NKT 128                          // 2 planes x 64 k-tiles
#define EPI_STR 65

__device__ __forceinline__ void ldsm_x4(uint32_t* r, uint32_t addr) {
    asm volatile("ldmatrix.sync.aligned.m8n8.x4.shared.b16 {%0,%1,%2,%3}, [%4];"
                 : "=r"(r[0]), "=r"(r[1]), "=r"(r[2]), "=r"(r[3]) : "r"(addr));
}

__device__ __forceinline__ void stage_load(uint32_t sbase, int stage, int kt,
                                           int tid, int m0, int n0) {
    const __half* Asrc = g_Ah + (size_t)m0 * Idim;
    const __half* Bsrc = (kt < 64 ? g_w1 : g_w0) + (size_t)n0 * Idim;
    int k0 = (kt & 63) * BK;
    uint32_t sA = sbase + (uint32_t)stage * STAGE_BYTES;
    uint32_t sB = sA + A_STG_B;
    {                                            // A: 64 rows x 4 chunks16B
        int r = tid >> 2, c = tid & 3;
        uint32_t d = sA + (uint32_t)(r * 80 + c * 16);
        asm volatile("cp.async.cg.shared.global [%0], [%1], 16;"
                     :: "r"(d), "l"(Asrc + (size_t)r * Idim + k0 + c * 8));
    }
#pragma unroll
    for (int i = 0; i < 2; i++) {                // B: 128 rows x 4 chunks16B
        int ch = tid + i * 256;
        int r = ch >> 2, c = ch & 3;
        uint32_t d = sB + (uint32_t)(r * 80 + c * 16);
        asm volatile("cp.async.cg.shared.global [%0], [%1], 16;"
                     :: "r"(d), "l"(Bsrc + (size_t)r * Idim + k0 + c * 8));
    }
}

__global__ __launch_bounds__(256, 4) void gemm_mma_kernel() {
    extern __shared__ char smem[];
    uint32_t sbase = (uint32_t)__cvta_generic_to_shared(smem);

    int tid  = threadIdx.x;
    int lane = tid & 31;
    int wid  = tid >> 5;
    int wm = (wid >> 1) * 16;            // 0,16,32,48
    int wn = (wid & 1) * 64;             // 0,64
    int lr = lane >> 2;
    int lc = lane & 3;
    int m0 = blockIdx.y * BM;
    int n0 = blockIdx.x * BN;

    int a_row  = wm + (lane & 15);
    int a_csel = (lane >> 4) << 3;
    int b_row  = ((lane >> 4) << 3) + (lane & 7);
    int b_csel = ((lane >> 3) & 1) << 3;

    float acc[8][4];
#pragma unroll
    for (int nt = 0; nt < 8; nt++)
#pragma unroll
        for (int q = 0; q < 4; q++) acc[nt][q] = 0.0f;

    stage_load(sbase, 0, 0, tid, m0, n0);
    asm volatile("cp.async.commit_group;" ::: "memory");
    stage_load(sbase, 1, 1, tid, m0, n0);
    asm volatile("cp.async.commit_group;" ::: "memory");

#pragma unroll 1
    for (int kt = 0; kt < NKT; kt++) {
        asm volatile("cp.async.wait_group 1;" ::: "memory");
        __syncthreads();

        if (kt + 2 < NKT)
            stage_load(sbase, (kt + 2) % 3, kt + 2, tid, m0, n0);
        asm volatile("cp.async.commit_group;" ::: "memory");

        if (kt == 64) {                  // plane boundary: acc = 2^-11 * C_res
#pragma unroll
            for (int nt = 0; nt < 8; nt++)
#pragma unroll
                for (int q = 0; q < 4; q++) acc[nt][q] *= 4.8828125e-4f;
        }

        uint32_t stA = sbase + (uint32_t)(kt % 3) * STAGE_BYTES;
        uint32_t stB = stA + A_STG_B;
#pragma unroll
        for (int ks = 0; ks < 2; ks++) {
            int kb = ks * 16;
            uint32_t a[4];
            ldsm_x4(a, stA + (uint32_t)(a_row * ASTR + kb + a_csel) * 2);
#pragma unroll
            for (int p = 0; p < 4; p++) {
                uint32_t r[4];
                ldsm_x4(r, stB + (uint32_t)((wn + p * 16 + b_row) * ASTR + kb + b_csel) * 2);
                float* c0 = acc[2 * p];
                asm volatile(
                    "mma.sync.aligned.m16n8k16.row.col.f32.f16.f16.f32 "
                    "{%0,%1,%2,%3}, {%4,%5,%6,%7}, {%8,%9}, {%0,%1,%2,%3};"
                    : "+f"(c0[0]), "+f"(c0[1]), "+f"(c0[2]), "+f"(c0[3])
                    : "r"(a[0]), "r"(a[1]), "r"(a[2]), "r"(a[3]),
                      "r"(r[0]), "r"(r[1]));
                float* c1 = acc[2 * p + 1];
                asm volatile(
                    "mma.sync.aligned.m16n8k16.row.col.f32.f16.f16.f32 "
                    "{%0,%1,%2,%3}, {%4,%5,%6,%7}, {%8,%9}, {%0,%1,%2,%3};"
                    : "+f"(c1[0]), "+f"(c1[1]), "+f"(c1[2]), "+f"(c1[3])
                    : "r"(a[0]), "r"(a[1]), "r"(a[2]), "r"(a[3]),
                      "r"(r[2]), "r"(r[3]));
            }
        }
    }

    // ---- Epilogue: BM=64 rows = all b for t = blockIdx.y; stage via smem ----
    __syncthreads();
    float* epi = reinterpret_cast<float*>(smem);   // [128 h][EPI_STR]
#pragma unroll
    for (int q2 = 0; q2 < 2; q2++) {
        int bb = wm + lr + q2 * 8;                 // b index 0..63
#pragma unroll
        for (int nt = 0; nt < 8; nt++) {
            int col = wn + nt * 8 + lc * 2;
            epi[(size_t)col * EPI_STR + bb]       = acc[nt][q2 * 2 + 0];
            epi[(size_t)(col + 1) * EPI_STR + bb] = acc[nt][q2 * 2 + 1];
        }
    }
    __syncthreads();
    {
        int h    = tid & 127;
        int half = tid >> 7;               // 0..1 (b 0..31 / 32..63)
        float* dst = g_weightedT + ((size_t)blockIdx.y * Hdim + n0 + h) * Bdim + half * 32;
        const float* src = epi + (size_t)h * EPI_STR + half * 32;
#pragma unroll
        for (int j = 0; j < 32; j += 4) {
            float4 o;
            o.x = src[j]; o.y = src[j + 1]; o.z = src[j + 2]; o.w = src[j + 3];
            *reinterpret_cast<float4*>(dst + j) = o;
        }
    }
}

// ---------------------------------------------------------------------------
// LIF scan: one warp per h, 8-deep rotating prefetch. (R13 verbatim)
// ---------------------------------------------------------------------------
__global__ __launch_bounds__(256) void scan_kernel(
    const float* __restrict__ threshold,
    const float* __restrict__ p_tau_mem, const float* __restrict__ p_tau_syn,
    const float* __restrict__ p_target,  const float* __restrict__ p_lr,
    float* __restrict__ out)
{
    int tid  = threadIdx.x;
    int lane = tid & 31;
    int h    = blockIdx.x * 8 + (tid >> 5);

    float tau_m = *p_tau_mem, tau_s = *p_tau_syn;
    float a_mem = (float)exp(-(double)(0.001f / tau_m));
    float a_syn = (float)exp(-(double)(0.001f / tau_s));
    float target = *p_target, lr = *p_lr;

    float thr = threshold[h];
    float fre = 0.0f;
    float isyn0 = 0.0f, v0 = 0.0f, isyn1 = 0.0f, v1 = 0.0f;
    unsigned sb0[4] = {0u, 0u, 0u, 0u};
    unsigned sb1[4] = {0u, 0u, 0u, 0u};

    const float* wptr = g_weightedT + (size_t)h * Bdim + lane * 2;
    const size_t TSTR = (size_t)Hdim * Bdim;

    float2 wbuf[8];
#pragma unroll
    for (int p = 0; p < 8; p++)
        wbuf[p] = *reinterpret_cast<const float2*>(wptr + p * TSTR);

#pragma unroll 8
    for (int t = 0; t < Tdim; ++t) {
        float2 w = wbuf[t & 7];
        if (t + 8 < Tdim)
            wbuf[t & 7] = *reinterpret_cast<const float2*>(wptr + (size_t)(t + 8) * TSTR);

        isyn0 = fmaf(a_syn, isyn0, w.x);
        v0    = fmaf(a_mem, v0, isyn0);
        isyn1 = fmaf(a_syn, isyn1, w.y);
        v1    = fmaf(a_mem, v1, isyn1);
        bool p0 = (v0 >= thr), p1 = (v1 >= thr);
        if (p0) { v0 -= thr; sb0[t >> 5] |= (1u << (t & 31)); }
        if (p1) { v1 -= thr; sb1[t >> 5] |= (1u << (t & 31)); }

        unsigned m0 = __ballot_sync(0xffffffffu, p0);
        unsigned m1 = __ballot_sync(0xffffffffu, p1);
        float s = (float)(__popc(m0) + __popc(m1));      // exact int

        float rate = s * (1.0f / 64.0f);
        fre = 0.99f * fre + 0.01f * rate;
        thr = thr + lr * (fre - target);
    }

    int bsel = (lane & 7) * 4;
#pragma unroll 4
    for (int bb = 0; bb < 64; ++bb) {
        int src = bb >> 1;
        unsigned w0, w1, w2, w3;
        if (bb & 1) {
            w0 = __shfl_sync(0xffffffffu, sb1[0], src);
            w1 = __shfl_sync(0xffffffffu, sb1[1], src);
            w2 = __shfl_sync(0xffffffffu, sb1[2], src);
            w3 = __shfl_sync(0xffffffffu, sb1[3], src);
        } else {
            w0 = __shfl_sync(0xffffffffu, sb0[0], src);
            w1 = __shfl_sync(0xffffffffu, sb0[1], src);
            w2 = __shfl_sync(0xffffffffu, sb0[2], src);
            w3 = __shfl_sync(0xffffffffu, sb0[3], src);
        }
        unsigned wsel = (lane < 8) ? w0 : (lane < 16) ? w1 : (lane < 24) ? w2 : w3;
        unsigned bits = (wsel >> bsel) & 0xFu;
        float4 o;
        o.x = (float)(bits & 1u);
        o.y = (float)((bits >> 1) & 1u);
        o.z = (float)((bits >> 2) & 1u);
        o.w = (float)((bits >> 3) & 1u);
        *reinterpret_cast<float4*>(
            out + ((size_t)bb * Hdim + h) * Tdim + lane * 4) = o;
    }
}

// ---------------------------------------------------------------------------
extern "C" void kernel_launch(void* const* d_in, const int* in_sizes, int n_in,
                              void* d_out, int out_size) {
    const float* spikes    = (const float*)d_in[0];
    const float* weight    = (const float*)d_in[1];
    const float* strength  = (const float*)d_in[2];
    const float* threshold = (const float*)d_in[3];
    const float* tau_mem   = (const float*)d_in[4];
    const float* tau_syn   = (const float*)d_in[5];
    const float* target    = (const float*)d_in[6];
    const float* lr        = (const float*)d_in[7];
    float* out = (float*)d_out;

    cudaFuncSetAttribute(gemm_mma_kernel,
                         cudaFuncAttributeMaxDynamicSharedMemorySize, GEMM_SMEM);

    prep_kernel<<<10240, dim3(32, 8)>>>(spikes, weight, strength);
    gemm_mma_kernel<<<dim3(Hdim / BN, Mtot / BM), 256, GEMM_SMEM>>>();
    scan_kernel<<<Hdim / 8, 256>>>(threshold, tau_mem, tau_syn, target, lr, out);
}

// round 15
// speedup vs baseline: 1.3156x; 1.3156x over previous
#include <cuda_runtime.h>
#include <cuda_fp16.h>
#include <cstdint>
#include <math.h>

#define Bdim 64
#define Idim 2048
#define Hdim 2048
#define Tdim 128
#define Mtot (Tdim * Bdim)          // 8192 rows (t,b)

// ---------------- scratch (device globals; allocation-free) ----------------
__device__ __half g_Ah[(size_t)Mtot * Idim];          // 32 MB  [t*B+b][i]
__device__ __half g_w0[(size_t)Hdim * Idim];          // 8 MB   hi plane [h][i]
__device__ __half g_w1[(size_t)Hdim * Idim];          // 8 MB   res*2^11 [h][i]
__device__ float  g_weightedT[(size_t)Tdim * Hdim * Bdim];  // 64 MB [t][h][b]

// ---------------------------------------------------------------------------
// Fused prep, 128B loads AND stores.
// ---------------------------------------------------------------------------
__global__ __launch_bounds__(256) void prep_kernel(const float* __restrict__ in,
                                                   const float* __restrict__ w,
                                                   const float* __restrict__ s) {
    __shared__ float tile[64][33];
    int bid = blockIdx.x;
    int tx = threadIdx.x, ty = threadIdx.y;
    int tid = ty * 32 + tx;
    int orow = tid >> 3;              // 0..31 output row
    int ic0  = (tid & 7) * 8;         // 0..56 i-column base

    if (bid < 8192) {
        int t0 = (bid & 3) * 32;
        int i0 = ((bid >> 2) & 31) * 64;
        int b  = bid >> 7;
#pragma unroll
        for (int j = 0; j < 8; j++)
            tile[ty + j * 8][tx] = in[((size_t)b * Idim + i0 + ty + j * 8) * Tdim + t0 + tx];
        __syncthreads();
        __half h[8];
#pragma unroll
        for (int q = 0; q < 8; q++)
            h[q] = __float2half_rn(tile[ic0 + q][orow]);
        *reinterpret_cast<uint4*>(
            g_Ah + ((size_t)(t0 + orow) * Bdim + b) * Idim + i0 + ic0)
            = *reinterpret_cast<uint4*>(h);
    } else {
        int sid = bid - 8192;
        int i0 = (sid & 31) * 64;
        int h0 = (sid >> 5) * 32;
#pragma unroll
        for (int j = 0; j < 8; j++) {
            size_t idx = (size_t)(i0 + ty + j * 8) * Hdim + h0 + tx;
            tile[ty + j * 8][tx] = w[idx] * s[idx];
        }
        __syncthreads();
        __half hh[8], hl[8];
#pragma unroll
        for (int q = 0; q < 8; q++) {
            float v = tile[ic0 + q][orow];
            __half hi = __float2half_rn(v);
            float r = v - __half2float(hi);             // exact (Fast2Sum)
            hh[q] = hi;
            hl[q] = __float2half_rn(r * 2048.0f);
        }
        size_t o = (size_t)(h0 + orow) * Idim + i0 + ic0;
        *reinterpret_cast<uint4*>(g_w0 + o) = *reinterpret_cast<uint4*>(hh);
        *reinterpret_cast<uint4*>(g_w1 + o) = *reinterpret_cast<uint4*>(hl);
    }
}

// ---------------------------------------------------------------------------
// mma.sync GEMM: C = A @ W0^T + 2^-11 * (A @ W1^T), fp32 acc.
// CTA 128x128, BK=64, 256 threads (8 warps, warp tile 32x64), 3-stage
// cp.async pipeline, ldmatrix.x4, fused 64-kt loop, 2 CTAs/SM.
// Measured at ~100% of the mma.sync issue-rate roofline on sm_103.
// ---------------------------------------------------------------------------
#define BM 128
#define BN 128
#define BK 64
#define ASTR 72                          // halves per smem row (144 B)
#define A_STG_H (BM * ASTR)
#define B_STG_H (BN * ASTR)
#define STAGE_BYTES ((A_STG_H + B_STG_H) * 2)   // 36864 B
#define GEMM_SMEM (3 * STAGE_BYTES)             // 110592 B
#define NKT 64
#define EPI_STR 65

__device__ __forceinline__ void ldsm_x4(uint32_t* r, uint32_t addr) {
    asm volatile("ldmatrix.sync.aligned.m8n8.x4.shared.b16 {%0,%1,%2,%3}, [%4];"
                 : "=r"(r[0]), "=r"(r[1]), "=r"(r[2]), "=r"(r[3]) : "r"(addr));
}

__device__ __forceinline__ void stage_load(uint32_t sbase, int stage, int kt,
                                           int tid, int m0, int n0) {
    const __half* Asrc = g_Ah + (size_t)m0 * Idim;
    const __half* Bsrc = (kt < 32 ? g_w1 : g_w0) + (size_t)n0 * Idim;
    int k0 = (kt & 31) * BK;
    uint32_t sA = sbase + (uint32_t)stage * STAGE_BYTES;
    uint32_t sB = sA + A_STG_H * 2;
#pragma unroll
    for (int i = 0; i < 4; i++) {
        int ch = tid + i * 256;
        int r = ch >> 3, c = ch & 7;
        uint32_t d = sA + (uint32_t)(r * ASTR + c * 8) * 2;
        asm volatile("cp.async.cg.shared.global [%0], [%1], 16;"
                     :: "r"(d), "l"(Asrc + (size_t)r * Idim + k0 + c * 8));
    }
#pragma unroll
    for (int i = 0; i < 4; i++) {
        int ch = tid + i * 256;
        int r = ch >> 3, c = ch & 7;
        uint32_t d = sB + (uint32_t)(r * ASTR + c * 8) * 2;
        asm volatile("cp.async.cg.shared.global [%0], [%1], 16;"
                     :: "r"(d), "l"(Bsrc + (size_t)r * Idim + k0 + c * 8));
    }
}

__global__ __launch_bounds__(256, 2) void gemm_mma_kernel() {
    extern __shared__ char smem[];
    uint32_t sbase = (uint32_t)__cvta_generic_to_shared(smem);

    int tid  = threadIdx.x;
    int lane = tid & 31;
    int wid  = tid >> 5;
    int wm = (wid >> 1) * 32;
    int wn = (wid & 1) * 64;
    int lr = lane >> 2;
    int lc = lane & 3;
    int m0 = blockIdx.y * BM;
    int n0 = blockIdx.x * BN;

    int a_row  = wm + (lane & 15);
    int a_csel = (lane >> 4) << 3;
    int b_row  = ((lane >> 4) << 3) + (lane & 7);
    int b_csel = ((lane >> 3) & 1) << 3;

    float acc[2][8][4];
#pragma unroll
    for (int mt = 0; mt < 2; mt++)
#pragma unroll
        for (int nt = 0; nt < 8; nt++)
#pragma unroll
            for (int q = 0; q < 4; q++) acc[mt][nt][q] = 0.0f;

    stage_load(sbase, 0, 0, tid, m0, n0);
    asm volatile("cp.async.commit_group;" ::: "memory");
    stage_load(sbase, 1, 1, tid, m0, n0);
    asm volatile("cp.async.commit_group;" ::: "memory");

#pragma unroll 1
    for (int kt = 0; kt < NKT; kt++) {
        asm volatile("cp.async.wait_group 1;" ::: "memory");
        __syncthreads();

        if (kt + 2 < NKT)
            stage_load(sbase, (kt + 2) % 3, kt + 2, tid, m0, n0);
        asm volatile("cp.async.commit_group;" ::: "memory");

        if (kt == 32) {                  // pass boundary: acc = 2^-11 * C_res
#pragma unroll
            for (int mt = 0; mt < 2; mt++)
#pragma unroll
                for (int nt = 0; nt < 8; nt++)
#pragma unroll
                    for (int q = 0; q < 4; q++) acc[mt][nt][q] *= 4.8828125e-4f;
        }

        uint32_t stA = sbase + (uint32_t)(kt % 3) * STAGE_BYTES;
        uint32_t stB = stA + A_STG_H * 2;
#pragma unroll
        for (int ks = 0; ks < 4; ks++) {
            int kb = ks * 16;
            uint32_t a[2][4];
#pragma unroll
            for (int mt = 0; mt < 2; mt++)
                ldsm_x4(a[mt], stA + (uint32_t)((a_row + mt * 16) * ASTR + kb + a_csel) * 2);
            uint32_t bf[8][2];
#pragma unroll
            for (int p = 0; p < 4; p++) {
                uint32_t r[4];
                ldsm_x4(r, stB + (uint32_t)((wn + p * 16 + b_row) * ASTR + kb + b_csel) * 2);
                bf[2 * p][0] = r[0]; bf[2 * p][1] = r[1];
                bf[2 * p + 1][0] = r[2]; bf[2 * p + 1][1] = r[3];
            }
#pragma unroll
            for (int nt = 0; nt < 8; nt++)
#pragma unroll
                for (int mt = 0; mt < 2; mt++) {
                    float* c = acc[mt][nt];
                    asm volatile(
                        "mma.sync.aligned.m16n8k16.row.col.f32.f16.f16.f32 "
                        "{%0,%1,%2,%3}, {%4,%5,%6,%7}, {%8,%9}, {%0,%1,%2,%3};"
                        : "+f"(c[0]), "+f"(c[1]), "+f"(c[2]), "+f"(c[3])
                        : "r"(a[mt][0]), "r"(a[mt][1]), "r"(a[mt][2]), "r"(a[mt][3]),
                          "r"(bf[nt][0]), "r"(bf[nt][1]));
                }
        }
    }

    __syncthreads();
    float* epi = reinterpret_cast<float*>(smem);
#pragma unroll
    for (int mt = 0; mt < 2; mt++) {
#pragma unroll
        for (int q2 = 0; q2 < 2; q2++) {
            int row = wm + mt * 16 + lr + q2 * 8;
            int tl = row >> 6, bb = row & 63;
#pragma unroll
            for (int nt = 0; nt < 8; nt++) {
                int col = wn + nt * 8 + lc * 2;
                epi[((size_t)(tl * 128 + col)     * EPI_STR) + bb] = acc[mt][nt][q2 * 2 + 0];
                epi[((size_t)(tl * 128 + col + 1) * EPI_STR) + bb] = acc[mt][nt][q2 * 2 + 1];
            }
        }
    }
    __syncthreads();
    {
        int tl = tid >> 7;
        int h  = tid & 127;
        int t_glob = blockIdx.y * 2 + tl;
        float* dst = g_weightedT + ((size_t)t_glob * Hdim + n0 + h) * Bdim;
        const float* src = epi + (size_t)(tl * 128 + h) * EPI_STR;
#pragma unroll
        for (int j = 0; j < 64; j += 4) {
            float4 o;
            o.x = src[j]; o.y = src[j + 1]; o.z = src[j + 2]; o.w = src[j + 3];
            *reinterpret_cast<float4*>(dst + j) = o;
        }
    }
}

// ---------------------------------------------------------------------------
// LIF scan: one warp per h, lanes own b = 2*lane, 2*lane+1.
// 8-deep rotating prefetch; ballot+popc exact sum; coalesced shfl output.
// ---------------------------------------------------------------------------
__global__ __launch_bounds__(256) void scan_kernel(
    const float* __restrict__ threshold,
    const float* __restrict__ p_tau_mem, const float* __restrict__ p_tau_syn,
    const float* __restrict__ p_target,  const float* __restrict__ p_lr,
    float* __restrict__ out)
{
    int tid  = threadIdx.x;
    int lane = tid & 31;
    int h    = blockIdx.x * 8 + (tid >> 5);

    float tau_m = *p_tau_mem, tau_s = *p_tau_syn;
    float a_mem = (float)exp(-(double)(0.001f / tau_m));
    float a_syn = (float)exp(-(double)(0.001f / tau_s));
    float target = *p_target, lr = *p_lr;

    float thr = threshold[h];
    float fre = 0.0f;
    float isyn0 = 0.0f, v0 = 0.0f, isyn1 = 0.0f, v1 = 0.0f;
    unsigned sb0[4] = {0u, 0u, 0u, 0u};
    unsigned sb1[4] = {0u, 0u, 0u, 0u};

    const float* wptr = g_weightedT + (size_t)h * Bdim + lane * 2;
    const size_t TSTR = (size_t)Hdim * Bdim;

    float2 wbuf[8];
#pragma unroll
    for (int p = 0; p < 8; p++)
        wbuf[p] = *reinterpret_cast<const float2*>(wptr + p * TSTR);

#pragma unroll 8
    for (int t = 0; t < Tdim; ++t) {
        float2 w = wbuf[t & 7];
        if (t + 8 < Tdim)
            wbuf[t & 7] = *reinterpret_cast<const float2*>(wptr + (size_t)(t + 8) * TSTR);

        isyn0 = fmaf(a_syn, isyn0, w.x);
        v0    = fmaf(a_mem, v0, isyn0);
        isyn1 = fmaf(a_syn, isyn1, w.y);
        v1    = fmaf(a_mem, v1, isyn1);
        bool p0 = (v0 >= thr), p1 = (v1 >= thr);
        if (p0) { v0 -= thr; sb0[t >> 5] |= (1u << (t & 31)); }
        if (p1) { v1 -= thr; sb1[t >> 5] |= (1u << (t & 31)); }

        unsigned m0 = __ballot_sync(0xffffffffu, p0);
        unsigned m1 = __ballot_sync(0xffffffffu, p1);
        float s = (float)(__popc(m0) + __popc(m1));      // exact int

        float rate = s * (1.0f / 64.0f);
        fre = 0.99f * fre + 0.01f * rate;
        thr = thr + lr * (fre - target);
    }

    int bsel = (lane & 7) * 4;
#pragma unroll 4
    for (int bb = 0; bb < 64; ++bb) {
        int src = bb >> 1;
        unsigned w0, w1, w2, w3;
        if (bb & 1) {
            w0 = __shfl_sync(0xffffffffu, sb1[0], src);
            w1 = __shfl_sync(0xffffffffu, sb1[1], src);
            w2 = __shfl_sync(0xffffffffu, sb1[2], src);
            w3 = __shfl_sync(0xffffffffu, sb1[3], src);
        } else {
            w0 = __shfl_sync(0xffffffffu, sb0[0], src);
            w1 = __shfl_sync(0xffffffffu, sb0[1], src);
            w2 = __shfl_sync(0xffffffffu, sb0[2], src);
            w3 = __shfl_sync(0xffffffffu, sb0[3], src);
        }
        unsigned wsel = (lane < 8) ? w0 : (lane < 16) ? w1 : (lane < 24) ? w2 : w3;
        unsigned bits = (wsel >> bsel) & 0xFu;
        float4 o;
        o.x = (float)(bits & 1u);
        o.y = (float)((bits >> 1) & 1u);
        o.z = (float)((bits >> 2) & 1u);
        o.w = (float)((bits >> 3) & 1u);
        *reinterpret_cast<float4*>(
            out + ((size_t)bb * Hdim + h) * Tdim + lane * 4) = o;
    }
}

// ---------------------------------------------------------------------------
extern "C" void kernel_launch(void* const* d_in, const int* in_sizes, int n_in,
                              void* d_out, int out_size) {
    const float* spikes    = (const float*)d_in[0];
    const float* weight    = (const float*)d_in[1];
    const float* strength  = (const float*)d_in[2];
    const float* threshold = (const float*)d_in[3];
    const float* tau_mem   = (const float*)d_in[4];
    const float* tau_syn   = (const float*)d_in[5];
    const float* target    = (const float*)d_in[6];
    const float* lr        = (const float*)d_in[7];
    float* out = (float*)d_out;

    cudaFuncSetAttribute(gemm_mma_kernel,
                         cudaFuncAttributeMaxDynamicSharedMemorySize, GEMM_SMEM);

    prep_kernel<<<10240, dim3(32, 8)>>>(spikes, weight, strength);
    gemm_mma_kernel<<<dim3(Hdim / BN, Mtot / BM), 256, GEMM_SMEM>>>();
    scan_kernel<<<Hdim / 8, 256>>>(threshold, tau_mem, tau_syn, target, lr, out);
}

// round 16
// speedup vs baseline: 1.3165x; 1.0006x over previous
#include <cuda_runtime.h>
#include <cuda_fp16.h>
#include <cstdint>
#include <math.h>

#define Bdim 64
#define Idim 2048
#define Hdim 2048
#define Tdim 128
#define Mtot (Tdim * Bdim)          // 8192 rows (t,b)

// ---------------- scratch (device globals; allocation-free) ----------------
__device__ __half g_Ah[(size_t)Mtot * Idim];          // 32 MB  [t*B+b][i]
__device__ __half g_w0[(size_t)Hdim * Idim];          // 8 MB   hi plane [h][i]
__device__ __half g_w1[(size_t)Hdim * Idim];          // 8 MB   res*2^11 [h][i]
__device__ float  g_weightedT[(size_t)Tdim * Hdim * Bdim];  // 64 MB [t][h][b]

// ---------------------------------------------------------------------------
// Fused prep, 128B loads AND stores. Read-once inputs use __ldcs (evict-first)
// so they don't evict the GEMM's operand planes from L2.
// ---------------------------------------------------------------------------
__global__ __launch_bounds__(256) void prep_kernel(const float* __restrict__ in,
                                                   const float* __restrict__ w,
                                                   const float* __restrict__ s) {
    __shared__ float tile[64][33];
    int bid = blockIdx.x;
    int tx = threadIdx.x, ty = threadIdx.y;
    int tid = ty * 32 + tx;
    int orow = tid >> 3;              // 0..31 output row
    int ic0  = (tid & 7) * 8;         // 0..56 i-column base

    if (bid < 8192) {
        int t0 = (bid & 3) * 32;
        int i0 = ((bid >> 2) & 31) * 64;
        int b  = bid >> 7;
#pragma unroll
        for (int j = 0; j < 8; j++)
            tile[ty + j * 8][tx] =
                __ldcs(in + ((size_t)b * Idim + i0 + ty + j * 8) * Tdim + t0 + tx);
        __syncthreads();
        __half h[8];
#pragma unroll
        for (int q = 0; q < 8; q++)
            h[q] = __float2half_rn(tile[ic0 + q][orow]);
        *reinterpret_cast<uint4*>(
            g_Ah + ((size_t)(t0 + orow) * Bdim + b) * Idim + i0 + ic0)
            = *reinterpret_cast<uint4*>(h);
    } else {
        int sid = bid - 8192;
        int i0 = (sid & 31) * 64;
        int h0 = (sid >> 5) * 32;
#pragma unroll
        for (int j = 0; j < 8; j++) {
            size_t idx = (size_t)(i0 + ty + j * 8) * Hdim + h0 + tx;
            tile[ty + j * 8][tx] = __ldcs(w + idx) * __ldcs(s + idx);
        }
        __syncthreads();
        __half hh[8], hl[8];
#pragma unroll
        for (int q = 0; q < 8; q++) {
            float v = tile[ic0 + q][orow];
            __half hi = __float2half_rn(v);
            float r = v - __half2float(hi);             // exact (Fast2Sum)
            hh[q] = hi;
            hl[q] = __float2half_rn(r * 2048.0f);
        }
        size_t o = (size_t)(h0 + orow) * Idim + i0 + ic0;
        *reinterpret_cast<uint4*>(g_w0 + o) = *reinterpret_cast<uint4*>(hh);
        *reinterpret_cast<uint4*>(g_w1 + o) = *reinterpret_cast<uint4*>(hl);
    }
}

// ---------------------------------------------------------------------------
// mma.sync GEMM: C = A @ W0^T + 2^-11 * (A @ W1^T), fp32 acc.
// CTA 128x128, BK=64, 256 threads (8 warps, warp tile 32x64), 3-stage
// cp.async pipeline, ldmatrix.x4, fused 64-kt loop, 2 CTAs/SM.
// Measured at ~100% of the mma.sync issue-rate roofline on sm_103.
// ---------------------------------------------------------------------------
#define BM 128
#define BN 128
#define BK 64
#define ASTR 72                          // halves per smem row (144 B)
#define A_STG_H (BM * ASTR)
#define B_STG_H (BN * ASTR)
#define STAGE_BYTES ((A_STG_H + B_STG_H) * 2)   // 36864 B
#define GEMM_SMEM (3 * STAGE_BYTES)             // 110592 B
#define NKT 64
#define EPI_STR 65

__device__ __forceinline__ void ldsm_x4(uint32_t* r, uint32_t addr) {
    asm volatile("ldmatrix.sync.aligned.m8n8.x4.shared.b16 {%0,%1,%2,%3}, [%4];"
                 : "=r"(r[0]), "=r"(r[1]), "=r"(r[2]), "=r"(r[3]) : "r"(addr));
}

__device__ __forceinline__ void stage_load(uint32_t sbase, int stage, int kt,
                                           int tid, int m0, int n0) {
    const __half* Asrc = g_Ah + (size_t)m0 * Idim;
    const __half* Bsrc = (kt < 32 ? g_w1 : g_w0) + (size_t)n0 * Idim;
    int k0 = (kt & 31) * BK;
    uint32_t sA = sbase + (uint32_t)stage * STAGE_BYTES;
    uint32_t sB = sA + A_STG_H * 2;
#pragma unroll
    for (int i = 0; i < 4; i++) {
        int ch = tid + i * 256;
        int r = ch >> 3, c = ch & 7;
        uint32_t d = sA + (uint32_t)(r * ASTR + c * 8) * 2;
        asm volatile("cp.async.cg.shared.global [%0], [%1], 16;"
                     :: "r"(d), "l"(Asrc + (size_t)r * Idim + k0 + c * 8));
    }
#pragma unroll
    for (int i = 0; i < 4; i++) {
        int ch = tid + i * 256;
        int r = ch >> 3, c = ch & 7;
        uint32_t d = sB + (uint32_t)(r * ASTR + c * 8) * 2;
        asm volatile("cp.async.cg.shared.global [%0], [%1], 16;"
                     :: "r"(d), "l"(Bsrc + (size_t)r * Idim + k0 + c * 8));
    }
}

__global__ __launch_bounds__(256, 2) void gemm_mma_kernel() {
    extern __shared__ char smem[];
    uint32_t sbase = (uint32_t)__cvta_generic_to_shared(smem);

    int tid  = threadIdx.x;
    int lane = tid & 31;
    int wid  = tid >> 5;
    int wm = (wid >> 1) * 32;
    int wn = (wid & 1) * 64;
    int lr = lane >> 2;
    int lc = lane & 3;
    int m0 = blockIdx.y * BM;
    int n0 = blockIdx.x * BN;

    int a_row  = wm + (lane & 15);
    int a_csel = (lane >> 4) << 3;
    int b_row  = ((lane >> 4) << 3) + (lane & 7);
    int b_csel = ((lane >> 3) & 1) << 3;

    float acc[2][8][4];
#pragma unroll
    for (int mt = 0; mt < 2; mt++)
#pragma unroll
        for (int nt = 0; nt < 8; nt++)
#pragma unroll
            for (int q = 0; q < 4; q++) acc[mt][nt][q] = 0.0f;

    stage_load(sbase, 0, 0, tid, m0, n0);
    asm volatile("cp.async.commit_group;" ::: "memory");
    stage_load(sbase, 1, 1, tid, m0, n0);
    asm volatile("cp.async.commit_group;" ::: "memory");

#pragma unroll 1
    for (int kt = 0; kt < NKT; kt++) {
        asm volatile("cp.async.wait_group 1;" ::: "memory");
        __syncthreads();

        if (kt + 2 < NKT)
            stage_load(sbase, (kt + 2) % 3, kt + 2, tid, m0, n0);
        asm volatile("cp.async.commit_group;" ::: "memory");

        if (kt == 32) {                  // pass boundary: acc = 2^-11 * C_res
#pragma unroll
            for (int mt = 0; mt < 2; mt++)
#pragma unroll
                for (int nt = 0; nt < 8; nt++)
#pragma unroll
                    for (int q = 0; q < 4; q++) acc[mt][nt][q] *= 4.8828125e-4f;
        }

        uint32_t stA = sbase + (uint32_t)(kt % 3) * STAGE_BYTES;
        uint32_t stB = stA + A_STG_H * 2;
#pragma unroll
        for (int ks = 0; ks < 4; ks++) {
            int kb = ks * 16;
            uint32_t a[2][4];
#pragma unroll
            for (int mt = 0; mt < 2; mt++)
                ldsm_x4(a[mt], stA + (uint32_t)((a_row + mt * 16) * ASTR + kb + a_csel) * 2);
            uint32_t bf[8][2];
#pragma unroll
            for (int p = 0; p < 4; p++) {
                uint32_t r[4];
                ldsm_x4(r, stB + (uint32_t)((wn + p * 16 + b_row) * ASTR + kb + b_csel) * 2);
                bf[2 * p][0] = r[0]; bf[2 * p][1] = r[1];
                bf[2 * p + 1][0] = r[2]; bf[2 * p + 1][1] = r[3];
            }
#pragma unroll
            for (int nt = 0; nt < 8; nt++)
#pragma unroll
                for (int mt = 0; mt < 2; mt++) {
                    float* c = acc[mt][nt];
                    asm volatile(
                        "mma.sync.aligned.m16n8k16.row.col.f32.f16.f16.f32 "
                        "{%0,%1,%2,%3}, {%4,%5,%6,%7}, {%8,%9}, {%0,%1,%2,%3};"
                        : "+f"(c[0]), "+f"(c[1]), "+f"(c[2]), "+f"(c[3])
                        : "r"(a[mt][0]), "r"(a[mt][1]), "r"(a[mt][2]), "r"(a[mt][3]),
                          "r"(bf[nt][0]), "r"(bf[nt][1]));
                }
        }
    }

    __syncthreads();
    float* epi = reinterpret_cast<float*>(smem);
#pragma unroll
    for (int mt = 0; mt < 2; mt++) {
#pragma unroll
        for (int q2 = 0; q2 < 2; q2++) {
            int row = wm + mt * 16 + lr + q2 * 8;
            int tl = row >> 6, bb = row & 63;
#pragma unroll
            for (int nt = 0; nt < 8; nt++) {
                int col = wn + nt * 8 + lc * 2;
                epi[((size_t)(tl * 128 + col)     * EPI_STR) + bb] = acc[mt][nt][q2 * 2 + 0];
                epi[((size_t)(tl * 128 + col + 1) * EPI_STR) + bb] = acc[mt][nt][q2 * 2 + 1];
            }
        }
    }
    __syncthreads();
    {
        int tl = tid >> 7;
        int h  = tid & 127;
        int t_glob = blockIdx.y * 2 + tl;
        float* dst = g_weightedT + ((size_t)t_glob * Hdim + n0 + h) * Bdim;
        const float* src = epi + (size_t)(tl * 128 + h) * EPI_STR;
#pragma unroll
        for (int j = 0; j < 64; j += 4) {
            float4 o;
            o.x = src[j]; o.y = src[j + 1]; o.z = src[j + 2]; o.w = src[j + 3];
            *reinterpret_cast<float4*>(dst + j) = o;
        }
    }
}

// ---------------------------------------------------------------------------
// LIF scan: one warp per h, lanes own b = 2*lane, 2*lane+1.
// 8-deep rotating prefetch; ballot+popc exact sum; coalesced shfl output.
// Output stores are streaming (__stcs) — nothing on-device re-reads them.
// ---------------------------------------------------------------------------
__global__ __launch_bounds__(256) void scan_kernel(
    const float* __restrict__ threshold,
    const float* __restrict__ p_tau_mem, const float* __restrict__ p_tau_syn,
    const float* __restrict__ p_target,  const float* __restrict__ p_lr,
    float* __restrict__ out)
{
    int tid  = threadIdx.x;
    int lane = tid & 31;
    int h    = blockIdx.x * 8 + (tid >> 5);

    float tau_m = *p_tau_mem, tau_s = *p_tau_syn;
    float a_mem = (float)exp(-(double)(0.001f / tau_m));
    float a_syn = (float)exp(-(double)(0.001f / tau_s));
    float target = *p_target, lr = *p_lr;

    float thr = threshold[h];
    float fre = 0.0f;
    float isyn0 = 0.0f, v0 = 0.0f, isyn1 = 0.0f, v1 = 0.0f;
    unsigned sb0[4] = {0u, 0u, 0u, 0u};
    unsigned sb1[4] = {0u, 0u, 0u, 0u};

    const float* wptr = g_weightedT + (size_t)h * Bdim + lane * 2;
    const size_t TSTR = (size_t)Hdim * Bdim;

    float2 wbuf[8];
#pragma unroll
    for (int p = 0; p < 8; p++)
        wbuf[p] = *reinterpret_cast<const float2*>(wptr + p * TSTR);

#pragma unroll 8
    for (int t = 0; t < Tdim; ++t) {
        float2 w = wbuf[t & 7];
        if (t + 8 < Tdim)
            wbuf[t & 7] = *reinterpret_cast<const float2*>(wptr + (size_t)(t + 8) * TSTR);

        isyn0 = fmaf(a_syn, isyn0, w.x);
        v0    = fmaf(a_mem, v0, isyn0);
        isyn1 = fmaf(a_syn, isyn1, w.y);
        v1    = fmaf(a_mem, v1, isyn1);
        bool p0 = (v0 >= thr), p1 = (v1 >= thr);
        if (p0) { v0 -= thr; sb0[t >> 5] |= (1u << (t & 31)); }
        if (p1) { v1 -= thr; sb1[t >> 5] |= (1u << (t & 31)); }

        unsigned m0 = __ballot_sync(0xffffffffu, p0);
        unsigned m1 = __ballot_sync(0xffffffffu, p1);
        float s = (float)(__popc(m0) + __popc(m1));      // exact int

        float rate = s * (1.0f / 64.0f);
        fre = 0.99f * fre + 0.01f * rate;
        thr = thr + lr * (fre - target);
    }

    int bsel = (lane & 7) * 4;
#pragma unroll 4
    for (int bb = 0; bb < 64; ++bb) {
        int src = bb >> 1;
        unsigned w0, w1, w2, w3;
        if (bb & 1) {
            w0 = __shfl_sync(0xffffffffu, sb1[0], src);
            w1 = __shfl_sync(0xffffffffu, sb1[1], src);
            w2 = __shfl_sync(0xffffffffu, sb1[2], src);
            w3 = __shfl_sync(0xffffffffu, sb1[3], src);
        } else {
            w0 = __shfl_sync(0xffffffffu, sb0[0], src);
            w1 = __shfl_sync(0xffffffffu, sb0[1], src);
            w2 = __shfl_sync(0xffffffffu, sb0[2], src);
            w3 = __shfl_sync(0xffffffffu, sb0[3], src);
        }
        unsigned wsel = (lane < 8) ? w0 : (lane < 16) ? w1 : (lane < 24) ? w2 : w3;
        unsigned bits = (wsel >> bsel) & 0xFu;
        float4 o;
        o.x = (float)(bits & 1u);
        o.y = (float)((bits >> 1) & 1u);
        o.z = (float)((bits >> 2) & 1u);
        o.w = (float)((bits >> 3) & 1u);
        __stcs(reinterpret_cast<float4*>(
                   out + ((size_t)bb * Hdim + h) * Tdim + lane * 4), o);
    }
}

// ---------------------------------------------------------------------------
extern "C" void kernel_launch(void* const* d_in, const int* in_sizes, int n_in,
                              void* d_out, int out_size) {
    const float* spikes    = (const float*)d_in[0];
    const float* weight    = (const float*)d_in[1];
    const float* strength  = (const float*)d_in[2];
    const float* threshold = (const float*)d_in[3];
    const float* tau_mem   = (const float*)d_in[4];
    const float* tau_syn   = (const float*)d_in[5];
    const float* target    = (const float*)d_in[6];
    const float* lr        = (const float*)d_in[7];
    float* out = (float*)d_out;

    cudaFuncSetAttribute(gemm_mma_kernel,
                         cudaFuncAttributeMaxDynamicSharedMemorySize, GEMM_SMEM);

    prep_kernel<<<10240, dim3(32, 8)>>>(spikes, weight, strength);
    gemm_mma_kernel<<<dim3(Hdim / BN, Mtot / BM), 256, GEMM_SMEM>>>();
    scan_kernel<<<Hdim / 8, 256>>>(threshold, tau_mem, tau_syn, target, lr, out);
}